// round 8
// baseline (speedup 1.0000x reference)
#include <cuda_runtime.h>
#include <cuda_fp16.h>

// Output layout (flattened jax pytree, each region N*16 f32 = n4 float4s):
//   region 0: -x + tanh(agg)
//   region 1: x
//   region 2: -x
//   region 3: agg (f32, upconverted from fp16 accumulator in final kernel)
//   region 4: tanh(agg)
//
// R8: 1 thread/edge. Front-batched loads (3 scalar + 4x LDG.128) give 4
// in-flight gathers/thread; 2x red.global.add.noftz.v4.f16x2 per edge keeps
// the RED lane-op floor at its R7 minimum while cutting LSU ops 12 -> 9/edge.

#define MAX_N 100000
__device__ uint4 g_x16[MAX_N * 2];    // fp16 copy of x: 32 B/node
__device__ uint4 g_agg16[MAX_N * 2];  // fp16 accumulators: 32 B/node

__device__ __forceinline__ unsigned pack_h2(float a, float b) {
    __half2 h = __floats2half2_rn(a, b);
    return *reinterpret_cast<unsigned*>(&h);
}

__device__ __forceinline__ float2 h2f(unsigned u) {
    __half2 h = *reinterpret_cast<__half2*>(&u);
    return __half22float2(h);
}

// Pack x -> fp16 and zero the fp16 accumulators.
__global__ void pack_kernel(const float4* __restrict__ x, int n4, int n2) {
    int i = blockIdx.x * blockDim.x + threadIdx.x;
    if (i < n2) g_agg16[i] = make_uint4(0u, 0u, 0u, 0u);
    if (i >= n4) return;
    float4 v = __ldg(&x[i]);
    ((uint2*)g_x16)[i] = make_uint2(pack_h2(v.x, v.y), pack_h2(v.z, v.w));
}

__device__ __forceinline__ unsigned msg_h2(float we, float2 a, float2 b) {
    return pack_h2(we * __sinf(a.x - b.x), we * __sinf(a.y - b.y));
}

// Edge scatter + region-1/2 copies fused (copy blocks overlap DRAM writes).
__global__ void edge_copy_kernel(const float4* __restrict__ x,
                                 const int* __restrict__ row,
                                 const int* __restrict__ col,
                                 const float* __restrict__ w,
                                 float4* __restrict__ out,
                                 int n4, int E, int edgeBlocks) {
    if (blockIdx.x >= edgeBlocks) {
        int i = (blockIdx.x - edgeBlocks) * blockDim.x + threadIdx.x;
        if (i < n4) {
            float4 v = __ldg(&x[i]);
            __stcs(&out[n4 + i], v);                                      // region 1
            __stcs(&out[2 * n4 + i],
                   make_float4(-v.x, -v.y, -v.z, -v.w));                  // region 2
        }
        return;
    }

    int e = blockIdx.x * blockDim.x + threadIdx.x;
    if (e >= E) return;

    int r    = __ldg(&row[e]);
    int cc   = __ldg(&col[e]);
    float we = __ldg(&w[e]);

    // Front-batch all 4 gathers (64 B total) for max memory-level parallelism.
    uint4 ur0 = __ldg(&g_x16[r  * 2]);
    uint4 ur1 = __ldg(&g_x16[r  * 2 + 1]);
    uint4 uc0 = __ldg(&g_x16[cc * 2]);
    uint4 uc1 = __ldg(&g_x16[cc * 2 + 1]);

    unsigned p0 = msg_h2(we, h2f(ur0.x), h2f(uc0.x));
    unsigned p1 = msg_h2(we, h2f(ur0.y), h2f(uc0.y));
    unsigned p2 = msg_h2(we, h2f(ur0.z), h2f(uc0.z));
    unsigned p3 = msg_h2(we, h2f(ur0.w), h2f(uc0.w));
    unsigned p4 = msg_h2(we, h2f(ur1.x), h2f(uc1.x));
    unsigned p5 = msg_h2(we, h2f(ur1.y), h2f(uc1.y));
    unsigned p6 = msg_h2(we, h2f(ur1.z), h2f(uc1.z));
    unsigned p7 = msg_h2(we, h2f(ur1.w), h2f(uc1.w));

    uint4* dst = &g_agg16[cc * 2];
    asm volatile("red.global.add.noftz.v4.f16x2 [%0], {%1, %2, %3, %4};"
                 :: "l"(dst), "r"(p0), "r"(p1), "r"(p2), "r"(p3)
                 : "memory");
    asm volatile("red.global.add.noftz.v4.f16x2 [%0], {%1, %2, %3, %4};"
                 :: "l"(dst + 1), "r"(p4), "r"(p5), "r"(p6), "r"(p7)
                 : "memory");
}

__global__ void final_kernel(const float4* __restrict__ x,
                             float4* __restrict__ out, int n4) {
    int i = blockIdx.x * blockDim.x + threadIdx.x;
    if (i >= n4) return;
    uint2 a16 = ((const uint2*)g_agg16)[i];     // 4 halves (L2-resident)
    float2 lo = h2f(a16.x), hi = h2f(a16.y);
    float4 a = make_float4(lo.x, lo.y, hi.x, hi.y);
    float4 v = __ldg(&x[i]);
    float4 t;
    t.x = tanhf(a.x); t.y = tanhf(a.y); t.z = tanhf(a.z); t.w = tanhf(a.w);
    __stcs(&out[3 * n4 + i], a);                                          // region 3
    __stcs(&out[4 * n4 + i], t);                                          // region 4
    __stcs(&out[i],
           make_float4(t.x - v.x, t.y - v.y, t.z - v.z, t.w - v.w));      // region 0
}

extern "C" void kernel_launch(void* const* d_in, const int* in_sizes, int n_in,
                              void* d_out, int out_size) {
    const float4* x   = (const float4*)d_in[0];
    const int*    row = (const int*)d_in[1];
    const int*    col = (const int*)d_in[2];
    const float*  w   = (const float*)d_in[3];

    int N  = in_sizes[0] / 16;   // 100000
    int E  = in_sizes[1];        // 3200000
    int n4 = N * 4;              // float4s per region
    int n2 = N * 2;              // uint4s in fp16 buffers

    float4* out = (float4*)d_out;

    pack_kernel<<<(n4 + 255) / 256, 256>>>(x, n4, n2);

    int edgeBlocks = (E + 255) / 256;     // 1 thread/edge
    int copyBlocks = (n4 + 255) / 256;
    edge_copy_kernel<<<edgeBlocks + copyBlocks, 256>>>(x, row, col, w,
                                                       out, n4, E, edgeBlocks);

    final_kernel<<<(n4 + 255) / 256, 256>>>(x, out, n4);
}

// round 9
// speedup vs baseline: 1.1666x; 1.1666x over previous
#include <cuda_runtime.h>
#include <cuda_fp16.h>

// Output layout (flattened jax pytree, each region N*16 f32 = n4 float4s):
//   region 0: -x + tanh(agg)
//   region 1: x
//   region 2: -x
//   region 3: agg (f32, upconverted from fp16 accumulator in final kernel)
//   region 4: tanh(agg)
//
// R9 = R7 (best, 57.7us) + __ldcs edge streams + zero-split so ncu's
// "-s 5 -c 1" (4th visible kernel) lands on edge_copy_kernel.

#define MAX_N 100000
__device__ uint4 g_x16[MAX_N * 2];    // fp16 copy of x: 32 B/node
__device__ uint4 g_agg16[MAX_N * 2];  // fp16 accumulators: 32 B/node

__device__ __forceinline__ unsigned pack_h2(float a, float b) {
    __half2 h = __floats2half2_rn(a, b);
    return *reinterpret_cast<unsigned*>(&h);
}

__device__ __forceinline__ float2 h2f(unsigned u) {
    __half2 h = *reinterpret_cast<__half2*>(&u);
    return __half22float2(h);
}

// Zero halves of the fp16 accumulator (split in two so the edge kernel is the
// 4th visible launch = ncu capture slot).
__global__ void zero_lo_kernel(int n2h) {
    int i = blockIdx.x * blockDim.x + threadIdx.x;
    if (i < n2h) g_agg16[i] = make_uint4(0u, 0u, 0u, 0u);
}
__global__ void zero_hi_kernel(int n2h, int n2) {
    int i = n2h + blockIdx.x * blockDim.x + threadIdx.x;
    if (i < n2) g_agg16[i] = make_uint4(0u, 0u, 0u, 0u);
}

// Pack x -> fp16.
__global__ void pack_kernel(const float4* __restrict__ x, int n4) {
    int i = blockIdx.x * blockDim.x + threadIdx.x;
    if (i >= n4) return;
    float4 v = __ldg(&x[i]);
    ((uint2*)g_x16)[i] = make_uint2(pack_h2(v.x, v.y), pack_h2(v.z, v.w));
}

// Edge scatter + region-1/2 copies fused (copy blocks overlap DRAM writes).
// 2 threads/edge, one 16B gather per endpoint per thread, one RED.v4.f16x2.
__global__ void edge_copy_kernel(const float4* __restrict__ x,
                                 const int* __restrict__ row,
                                 const int* __restrict__ col,
                                 const float* __restrict__ w,
                                 float4* __restrict__ out,
                                 int n4, int E, int edgeBlocks) {
    if (blockIdx.x >= edgeBlocks) {
        int i = (blockIdx.x - edgeBlocks) * blockDim.x + threadIdx.x;
        if (i < n4) {
            float4 v = __ldg(&x[i]);
            __stcs(&out[n4 + i], v);                                      // region 1
            __stcs(&out[2 * n4 + i],
                   make_float4(-v.x, -v.y, -v.z, -v.w));                  // region 2
        }
        return;
    }

    int t = blockIdx.x * blockDim.x + threadIdx.x;
    int e = t >> 1;
    if (e >= E) return;
    int h = t & 1;                        // 2 threads/edge, 8 dims each

    // Single-use streams: evict-first so they don't displace x/agg in L2.
    int r    = __ldcs(&row[e]);
    int cc   = __ldcs(&col[e]);
    float we = __ldcs(&w[e]);

    // One 16 B load per endpoint per thread (8 fp16 dims).
    uint4 ur = __ldg(&g_x16[r  * 2 + h]);
    uint4 uc = __ldg(&g_x16[cc * 2 + h]);

    float2 a0 = h2f(ur.x), a1 = h2f(ur.y), a2 = h2f(ur.z), a3 = h2f(ur.w);
    float2 b0 = h2f(uc.x), b1 = h2f(uc.y), b2 = h2f(uc.z), b3 = h2f(uc.w);

    unsigned p0 = pack_h2(we * __sinf(a0.x - b0.x), we * __sinf(a0.y - b0.y));
    unsigned p1 = pack_h2(we * __sinf(a1.x - b1.x), we * __sinf(a1.y - b1.y));
    unsigned p2 = pack_h2(we * __sinf(a2.x - b2.x), we * __sinf(a2.y - b2.y));
    unsigned p3 = pack_h2(we * __sinf(a3.x - b3.x), we * __sinf(a3.y - b3.y));

    uint4* dst = &g_agg16[cc * 2 + h];
    asm volatile("red.global.add.noftz.v4.f16x2 [%0], {%1, %2, %3, %4};"
                 :: "l"(dst), "r"(p0), "r"(p1), "r"(p2), "r"(p3)
                 : "memory");
}

__global__ void final_kernel(const float4* __restrict__ x,
                             float4* __restrict__ out, int n4) {
    int i = blockIdx.x * blockDim.x + threadIdx.x;
    if (i >= n4) return;
    uint2 a16 = ((const uint2*)g_agg16)[i];     // 4 halves (L2-resident)
    float2 lo = h2f(a16.x), hi = h2f(a16.y);
    float4 a = make_float4(lo.x, lo.y, hi.x, hi.y);
    float4 v = __ldg(&x[i]);
    float4 t;
    t.x = tanhf(a.x); t.y = tanhf(a.y); t.z = tanhf(a.z); t.w = tanhf(a.w);
    __stcs(&out[3 * n4 + i], a);                                          // region 3
    __stcs(&out[4 * n4 + i], t);                                          // region 4
    __stcs(&out[i],
           make_float4(t.x - v.x, t.y - v.y, t.z - v.z, t.w - v.w));      // region 0
}

extern "C" void kernel_launch(void* const* d_in, const int* in_sizes, int n_in,
                              void* d_out, int out_size) {
    const float4* x   = (const float4*)d_in[0];
    const int*    row = (const int*)d_in[1];
    const int*    col = (const int*)d_in[2];
    const float*  w   = (const float*)d_in[3];

    int N  = in_sizes[0] / 16;   // 100000
    int E  = in_sizes[1];        // 3200000
    int n4 = N * 4;              // float4s per region
    int n2 = N * 2;              // uint4s in fp16 buffers
    int n2h = n2 / 2;

    float4* out = (float4*)d_out;

    zero_lo_kernel<<<(n2h + 255) / 256, 256>>>(n2h);                 // visible 0
    zero_hi_kernel<<<(n2 - n2h + 255) / 256, 256>>>(n2h, n2);        // visible 1
    pack_kernel<<<(n4 + 255) / 256, 256>>>(x, n4);                   // visible 2

    int edgeBlocks = (2 * E + 255) / 256;   // 2 threads/edge
    int copyBlocks = (n4 + 255) / 256;
    edge_copy_kernel<<<edgeBlocks + copyBlocks, 256>>>(x, row, col, w,
                                                       out, n4, E, edgeBlocks); // visible 3 = ncu slot

    final_kernel<<<(n4 + 255) / 256, 256>>>(x, out, n4);             // visible 4
}

// round 10
// speedup vs baseline: 1.1716x; 1.0043x over previous
#include <cuda_runtime.h>
#include <cuda_fp16.h>

// Output layout (flattened jax pytree, each region N*16 f32 = n4 float4s):
//   region 0: -x + tanh(agg)   region 1: x   region 2: -x
//   region 3: agg (f32, from fp16 accumulator)   region 4: tanh(agg)
//
// R10: edge kernel is L1tex-wavefront-bound (83.7% in R9). Wavefronts/edge are
// at the structural floor (2 gathers + 1 RED), so raise pipe utilization with
// ILP: 2 edges per thread (strided), lane-pair layout preserved so each edge's
// 32B node record is one combined wavefront per endpoint.

#define MAX_N 100000
__device__ uint4 g_x16[MAX_N * 2];    // fp16 copy of x: 32 B/node
__device__ uint4 g_agg16[MAX_N * 2];  // fp16 accumulators: 32 B/node

__device__ __forceinline__ unsigned pack_h2(float a, float b) {
    __half2 h = __floats2half2_rn(a, b);
    return *reinterpret_cast<unsigned*>(&h);
}

__device__ __forceinline__ float2 h2f(unsigned u) {
    __half2 h = *reinterpret_cast<__half2*>(&u);
    return __half22float2(h);
}

// Zero split in two so edge_copy_kernel stays at ncu capture slot (visible #3).
__global__ void zero_lo_kernel(int n2h) {
    int i = blockIdx.x * blockDim.x + threadIdx.x;
    if (i < n2h) g_agg16[i] = make_uint4(0u, 0u, 0u, 0u);
}
__global__ void zero_hi_kernel(int n2h, int n2) {
    int i = n2h + blockIdx.x * blockDim.x + threadIdx.x;
    if (i < n2) g_agg16[i] = make_uint4(0u, 0u, 0u, 0u);
}

__global__ void pack_kernel(const float4* __restrict__ x, int n4) {
    int i = blockIdx.x * blockDim.x + threadIdx.x;
    if (i >= n4) return;
    float4 v = __ldg(&x[i]);
    ((uint2*)g_x16)[i] = make_uint2(pack_h2(v.x, v.y), pack_h2(v.z, v.w));
}

__device__ __forceinline__ void msgs(float we, const uint4& ur, const uint4& uc,
                                     unsigned& p0, unsigned& p1,
                                     unsigned& p2, unsigned& p3) {
    float2 a0 = h2f(ur.x), a1 = h2f(ur.y), a2 = h2f(ur.z), a3 = h2f(ur.w);
    float2 b0 = h2f(uc.x), b1 = h2f(uc.y), b2 = h2f(uc.z), b3 = h2f(uc.w);
    p0 = pack_h2(we * __sinf(a0.x - b0.x), we * __sinf(a0.y - b0.y));
    p1 = pack_h2(we * __sinf(a1.x - b1.x), we * __sinf(a1.y - b1.y));
    p2 = pack_h2(we * __sinf(a2.x - b2.x), we * __sinf(a2.y - b2.y));
    p3 = pack_h2(we * __sinf(a3.x - b3.x), we * __sinf(a3.y - b3.y));
}

#define RED_V4F16X2(dst, p0, p1, p2, p3)                                    \
    asm volatile("red.global.add.noftz.v4.f16x2 [%0], {%1, %2, %3, %4};"    \
                 :: "l"(dst), "r"(p0), "r"(p1), "r"(p2), "r"(p3) : "memory")

// Edge scatter (2 edges/thread, 2 threads/edge) + region-1/2 copies fused.
__global__ void edge_copy_kernel(const float4* __restrict__ x,
                                 const int* __restrict__ row,
                                 const int* __restrict__ col,
                                 const float* __restrict__ w,
                                 float4* __restrict__ out,
                                 int n4, int E, int edgeBlocks) {
    if (blockIdx.x >= edgeBlocks) {
        int i = (blockIdx.x - edgeBlocks) * blockDim.x + threadIdx.x;
        if (i < n4) {
            float4 v = __ldg(&x[i]);
            __stcs(&out[n4 + i], v);                                      // region 1
            __stcs(&out[2 * n4 + i],
                   make_float4(-v.x, -v.y, -v.z, -v.w));                  // region 2
        }
        return;
    }

    int t = blockIdx.x * blockDim.x + threadIdx.x;
    int p = t >> 1;                  // pair index: edges p and p+Eh
    int h = t & 1;                   // lane-pair half: 8 dims each
    int Eh = (E + 1) >> 1;
    if (p >= Eh) return;
    int eB = p + Eh;
    bool hasB = eB < E;

    // Scalar streams (evict-first; lane-pair duplicates broadcast-combine).
    int   rA = __ldcs(&row[p]);
    int   cA = __ldcs(&col[p]);
    float wA = __ldcs(&w[p]);
    int rB = rA, cB = cA; float wB = 0.f;
    if (hasB) { rB = __ldcs(&row[eB]); cB = __ldcs(&col[eB]); wB = __ldcs(&w[eB]); }

    // Front-batch 4 independent 16 B gathers (MLP=4).
    uint4 urA = __ldg(&g_x16[rA * 2 + h]);
    uint4 ucA = __ldg(&g_x16[cA * 2 + h]);
    uint4 urB = __ldg(&g_x16[rB * 2 + h]);
    uint4 ucB = __ldg(&g_x16[cB * 2 + h]);

    unsigned pa0, pa1, pa2, pa3, pb0, pb1, pb2, pb3;
    msgs(wA, urA, ucA, pa0, pa1, pa2, pa3);
    msgs(wB, urB, ucB, pb0, pb1, pb2, pb3);

    RED_V4F16X2(&g_agg16[cA * 2 + h], pa0, pa1, pa2, pa3);
    if (hasB) RED_V4F16X2(&g_agg16[cB * 2 + h], pb0, pb1, pb2, pb3);
}

__global__ void final_kernel(const float4* __restrict__ x,
                             float4* __restrict__ out, int n4) {
    int i = blockIdx.x * blockDim.x + threadIdx.x;
    if (i >= n4) return;
    uint2 a16 = ((const uint2*)g_agg16)[i];     // 4 halves (L2-resident)
    float2 lo = h2f(a16.x), hi = h2f(a16.y);
    float4 a = make_float4(lo.x, lo.y, hi.x, hi.y);
    float4 v = __ldg(&x[i]);
    float4 t;
    t.x = tanhf(a.x); t.y = tanhf(a.y); t.z = tanhf(a.z); t.w = tanhf(a.w);
    __stcs(&out[3 * n4 + i], a);                                          // region 3
    __stcs(&out[4 * n4 + i], t);                                          // region 4
    __stcs(&out[i],
           make_float4(t.x - v.x, t.y - v.y, t.z - v.z, t.w - v.w));      // region 0
}

extern "C" void kernel_launch(void* const* d_in, const int* in_sizes, int n_in,
                              void* d_out, int out_size) {
    const float4* x   = (const float4*)d_in[0];
    const int*    row = (const int*)d_in[1];
    const int*    col = (const int*)d_in[2];
    const float*  w   = (const float*)d_in[3];

    int N  = in_sizes[0] / 16;   // 100000
    int E  = in_sizes[1];        // 3200000
    int n4 = N * 4;
    int n2 = N * 2;
    int n2h = n2 / 2;

    float4* out = (float4*)d_out;

    zero_lo_kernel<<<(n2h + 255) / 256, 256>>>(n2h);              // visible 0
    zero_hi_kernel<<<(n2 - n2h + 255) / 256, 256>>>(n2h, n2);     // visible 1
    pack_kernel<<<(n4 + 255) / 256, 256>>>(x, n4);                // visible 2

    int Eh = (E + 1) >> 1;
    int edgeThreads = 2 * Eh;                   // 2 threads/edge-pair
    int edgeBlocks = (edgeThreads + 255) / 256;
    int copyBlocks = (n4 + 255) / 256;
    edge_copy_kernel<<<edgeBlocks + copyBlocks, 256>>>(x, row, col, w,
                                                       out, n4, E, edgeBlocks); // visible 3 = ncu slot

    final_kernel<<<(n4 + 255) / 256, 256>>>(x, out, n4);          // visible 4
}

// round 11
// speedup vs baseline: 1.2171x; 1.0389x over previous
#include <cuda_runtime.h>
#include <cuda_fp16.h>

// Output layout (flattened jax pytree, each region N*16 f32 = n4 float4s):
//   region 0: -x + tanh(agg)   region 1: x   region 2: -x
//   region 3: agg (f32, from fp16 accumulator)   region 4: tanh(agg)
//
// R11 = best-of: R10's 2-edges/thread lane-pair ILP (edge L1tex-bound, 88.3%)
// + R7's plain __ldg on edge streams (ldcs cost ~5us) + fused pack/zero
// (drops 2 launch overheads). 3 kernels total.

#define MAX_N 100000
__device__ uint4 g_x16[MAX_N * 2];    // fp16 copy of x: 32 B/node
__device__ uint4 g_agg16[MAX_N * 2];  // fp16 accumulators: 32 B/node

__device__ __forceinline__ unsigned pack_h2(float a, float b) {
    __half2 h = __floats2half2_rn(a, b);
    return *reinterpret_cast<unsigned*>(&h);
}

__device__ __forceinline__ float2 h2f(unsigned u) {
    __half2 h = *reinterpret_cast<__half2*>(&u);
    return __half22float2(h);
}

// Pack x -> fp16 and zero the fp16 accumulators (one pass).
__global__ void pack_kernel(const float4* __restrict__ x, int n4, int n2) {
    int i = blockIdx.x * blockDim.x + threadIdx.x;
    if (i < n2) g_agg16[i] = make_uint4(0u, 0u, 0u, 0u);
    if (i >= n4) return;
    float4 v = __ldg(&x[i]);
    ((uint2*)g_x16)[i] = make_uint2(pack_h2(v.x, v.y), pack_h2(v.z, v.w));
}

__device__ __forceinline__ void msgs(float we, const uint4& ur, const uint4& uc,
                                     unsigned& p0, unsigned& p1,
                                     unsigned& p2, unsigned& p3) {
    float2 a0 = h2f(ur.x), a1 = h2f(ur.y), a2 = h2f(ur.z), a3 = h2f(ur.w);
    float2 b0 = h2f(uc.x), b1 = h2f(uc.y), b2 = h2f(uc.z), b3 = h2f(uc.w);
    p0 = pack_h2(we * __sinf(a0.x - b0.x), we * __sinf(a0.y - b0.y));
    p1 = pack_h2(we * __sinf(a1.x - b1.x), we * __sinf(a1.y - b1.y));
    p2 = pack_h2(we * __sinf(a2.x - b2.x), we * __sinf(a2.y - b2.y));
    p3 = pack_h2(we * __sinf(a3.x - b3.x), we * __sinf(a3.y - b3.y));
}

#define RED_V4F16X2(dst, p0, p1, p2, p3)                                    \
    asm volatile("red.global.add.noftz.v4.f16x2 [%0], {%1, %2, %3, %4};"    \
                 :: "l"(dst), "r"(p0), "r"(p1), "r"(p2), "r"(p3) : "memory")

// Edge scatter (2 edges/thread, 2 threads/edge, lane-pair sector-combined)
// + region-1/2 copies fused (overlap the latency-bound edge phase).
__global__ void edge_copy_kernel(const float4* __restrict__ x,
                                 const int* __restrict__ row,
                                 const int* __restrict__ col,
                                 const float* __restrict__ w,
                                 float4* __restrict__ out,
                                 int n4, int E, int edgeBlocks) {
    if (blockIdx.x >= edgeBlocks) {
        int i = (blockIdx.x - edgeBlocks) * blockDim.x + threadIdx.x;
        if (i < n4) {
            float4 v = __ldg(&x[i]);
            __stcs(&out[n4 + i], v);                                      // region 1
            __stcs(&out[2 * n4 + i],
                   make_float4(-v.x, -v.y, -v.z, -v.w));                  // region 2
        }
        return;
    }

    int t = blockIdx.x * blockDim.x + threadIdx.x;
    int p = t >> 1;                  // pair index: edges p and p+Eh
    int h = t & 1;                   // lane-pair half: 8 dims each
    int Eh = (E + 1) >> 1;
    if (p >= Eh) return;
    int eB = p + Eh;
    bool hasB = eB < E;

    int   rA = __ldg(&row[p]);
    int   cA = __ldg(&col[p]);
    float wA = __ldg(&w[p]);
    int rB = rA, cB = cA; float wB = 0.f;
    if (hasB) { rB = __ldg(&row[eB]); cB = __ldg(&col[eB]); wB = __ldg(&w[eB]); }

    // Front-batch 4 independent 16 B gathers (MLP=4); lanes 2i/2i+1 of an
    // edge hit the same 32 B sector -> 1 wavefront per endpoint per edge.
    uint4 urA = __ldg(&g_x16[rA * 2 + h]);
    uint4 ucA = __ldg(&g_x16[cA * 2 + h]);
    uint4 urB = __ldg(&g_x16[rB * 2 + h]);
    uint4 ucB = __ldg(&g_x16[cB * 2 + h]);

    unsigned pa0, pa1, pa2, pa3, pb0, pb1, pb2, pb3;
    msgs(wA, urA, ucA, pa0, pa1, pa2, pa3);
    msgs(wB, urB, ucB, pb0, pb1, pb2, pb3);

    RED_V4F16X2(&g_agg16[cA * 2 + h], pa0, pa1, pa2, pa3);
    if (hasB) RED_V4F16X2(&g_agg16[cB * 2 + h], pb0, pb1, pb2, pb3);
}

__global__ void final_kernel(const float4* __restrict__ x,
                             float4* __restrict__ out, int n4) {
    int i = blockIdx.x * blockDim.x + threadIdx.x;
    if (i >= n4) return;
    uint2 a16 = ((const uint2*)g_agg16)[i];     // 4 halves (L2-resident)
    float2 lo = h2f(a16.x), hi = h2f(a16.y);
    float4 a = make_float4(lo.x, lo.y, hi.x, hi.y);
    float4 v = __ldg(&x[i]);
    float4 t;
    t.x = tanhf(a.x); t.y = tanhf(a.y); t.z = tanhf(a.z); t.w = tanhf(a.w);
    __stcs(&out[3 * n4 + i], a);                                          // region 3
    __stcs(&out[4 * n4 + i], t);                                          // region 4
    __stcs(&out[i],
           make_float4(t.x - v.x, t.y - v.y, t.z - v.z, t.w - v.w));      // region 0
}

extern "C" void kernel_launch(void* const* d_in, const int* in_sizes, int n_in,
                              void* d_out, int out_size) {
    const float4* x   = (const float4*)d_in[0];
    const int*    row = (const int*)d_in[1];
    const int*    col = (const int*)d_in[2];
    const float*  w   = (const float*)d_in[3];

    int N  = in_sizes[0] / 16;   // 100000
    int E  = in_sizes[1];        // 3200000
    int n4 = N * 4;
    int n2 = N * 2;

    float4* out = (float4*)d_out;

    pack_kernel<<<(n4 + 255) / 256, 256>>>(x, n4, n2);

    int Eh = (E + 1) >> 1;
    int edgeThreads = 2 * Eh;                   // 2 threads per edge-pair
    int edgeBlocks = (edgeThreads + 255) / 256;
    int copyBlocks = (n4 + 255) / 256;
    edge_copy_kernel<<<edgeBlocks + copyBlocks, 256>>>(x, row, col, w,
                                                       out, n4, E, edgeBlocks);

    final_kernel<<<(n4 + 255) / 256, 256>>>(x, out, n4);
}